// round 11
// baseline (speedup 1.0000x reference)
#include <cuda_runtime.h>
#include <cuda_bf16.h>
#include <cstdint>
#include <math.h>

#define NB 4
#define NPT 4096
#define NF 256
#define NTOT (NB*NPT)
#define DS 80
#define NTILE 32
#define NTRI (NTILE*(NTILE+1)/2)

__device__ __nv_bfloat16 g_bf[(size_t)NTOT * NF];
__device__ float g_sq[NTOT];
__device__ int g_p[NTOT], g_q[NTOT], g_labval[NTOT];
__device__ int g_ptrA[NTOT], g_ptrB[NTOT], g_labels[NTOT];
__device__ int g_ccnt[64], g_coff[64];
__device__ int g_barrier[8];
__device__ int g_hist[NB][NTOT + 1];
__device__ int g_map[NB][NTOT + 1];
__device__ int g_members[NTOT];
__device__ int g_clusM[NTOT], g_clusB[NTOT], g_clusBase[NTOT], g_clusL[NTOT];
__device__ int g_Kb[NB], g_KbBase[NB], g_Ktot, g_Rtot;
__device__ int g_gidx[(size_t)NTOT * DS];

__device__ __forceinline__ uint32_t smem_u32(const void* p) {
    uint32_t a;
    asm("{ .reg .u64 t; cvta.to.shared.u64 t, %1; cvt.u32.u64 %0, t; }" : "=r"(a) : "l"(p));
    return a;
}
__device__ __forceinline__ void cp16(uint32_t dst, const void* src) {
    asm volatile("cp.async.ca.shared.global [%0], [%1], 16;" :: "r"(dst), "l"(src));
}
__device__ __forceinline__ void cp_commit() { asm volatile("cp.async.commit_group;"); }
__device__ __forceinline__ void cp_wait1() { asm volatile("cp.async.wait_group 1;"); }
__device__ __forceinline__ void ldsm4(uint32_t* r, uint32_t a) {
    asm volatile("ldmatrix.sync.aligned.m8n8.x4.shared.b16 {%0,%1,%2,%3}, [%4];"
        : "=r"(r[0]), "=r"(r[1]), "=r"(r[2]), "=r"(r[3]) : "r"(a));
}
__device__ __forceinline__ void ldsm2(uint32_t* r, uint32_t a) {
    asm volatile("ldmatrix.sync.aligned.m8n8.x2.shared.b16 {%0,%1}, [%2];"
        : "=r"(r[0]), "=r"(r[1]) : "r"(a));
}
__device__ __forceinline__ void mma16816(float* c, const uint32_t* a, const uint32_t* b) {
    asm volatile("mma.sync.aligned.m16n8k16.row.col.f32.bf16.bf16.f32 "
        "{%0,%1,%2,%3},{%4,%5,%6,%7},{%8,%9},{%0,%1,%2,%3};"
        : "+f"(c[0]), "+f"(c[1]), "+f"(c[2]), "+f"(c[3])
        : "r"(a[0]), "r"(a[1]), "r"(a[2]), "r"(a[3]), "r"(b[0]), "r"(b[1]));
}

#define STR 80
#define STG 20480
#define T_A 0
#define T_B 10240
#define OFF_SQJ 61440
#define OFF_MQ 61952
#define OFF_MP 62464
#define OFF_MT 62976
#define SMEM_DYN 63488

// ---- 1: fused fp32->bf16 convert + row sumsq + p/q + barrier init ----
__global__ void k_cvtsq(const float* __restrict__ feat, float* __restrict__ out) {
    int gt = blockIdx.x * blockDim.x + threadIdx.x;
    if (gt == 0) out[0] = 0.f;
    if (gt < 8) g_barrier[gt] = 0;
    if (gt < NTOT) { g_p[gt] = -1; g_q[gt] = -1; }
    int w = gt >> 5, lane = gt & 31;
    const float* r = feat + (size_t)w * NF;
    __nv_bfloat16* d = g_bf + (size_t)w * NF;
    float s = 0.f;
#pragma unroll
    for (int t = 0; t < NF / 32; t++) {
        float x = r[t * 32 + lane];
        s = fmaf(x, x, s);
        d[t * 32 + lane] = __float2bfloat16_rn(x);
    }
#pragma unroll
    for (int o = 16; o; o >>= 1) s += __shfl_xor_sync(0xffffffffu, s, o);
    if (lane == 0) g_sq[w] = s;
}

// ---- 2: bf16 HMMA GEMM, 3-stage cp.async, epilogue -> p/q atomicMax ----
__global__ __launch_bounds__(256, 2) void k_mma() {
    extern __shared__ char sb[];
    uint32_t s0 = smem_u32(sb);
    int t = threadIdx.x, wid = t >> 5, l = t & 31;
    int wm = wid >> 2, wn = wid & 3;
    int ti = blockIdx.x, bi = 0;
    while (ti >= NTILE - bi) { ti -= NTILE - bi; bi++; }
    int bj = bi + ti;
    int b = blockIdx.y;
    int iBase = bi * 128, jBase = bj * 128;
    bool diag = (bi == bj);

    if (t < 128) {
        ((float*)(sb + OFF_SQJ))[t] = g_sq[b * NPT + jBase + t];
        ((int*)(sb + OFF_MQ))[t] = -1;
        ((int*)(sb + OFF_MP))[t] = -1;
        ((int*)(sb + OFF_MT))[t] = -1;
    }

    const __nv_bfloat16* A = g_bf + (size_t)(b * NPT + iBase) * NF;
    const __nv_bfloat16* B = g_bf + (size_t)(b * NPT + jBase) * NF;

    float acc[4][4][4];
#pragma unroll
    for (int mt = 0; mt < 4; mt++)
#pragma unroll
        for (int nt = 0; nt < 4; nt++)
#pragma unroll
            for (int r = 0; r < 4; r++) acc[mt][nt][r] = 0.f;

    int row = t >> 1, half = t & 1;
    uint32_t dce = s0 + row * STR + half * 32;
    size_t gce = (size_t)row * NF + half * 16;
    cp16(dce + T_A, A + gce); cp16(dce + T_A + 16, A + gce + 8);
    cp16(dce + T_B, B + gce); cp16(dce + T_B + 16, B + gce + 8);
    cp_commit();
    cp16(dce + STG + T_A, A + gce + 32); cp16(dce + STG + T_A + 16, A + gce + 40);
    cp16(dce + STG + T_B, B + gce + 32); cp16(dce + STG + T_B + 16, B + gce + 40);
    cp_commit();
#pragma unroll 1
    for (int c = 0; c < 8; c++) {
        cp_wait1();
        __syncthreads();
        if (c < 6) {
            uint32_t d = dce + ((c + 2) % 3) * STG;
            size_t g2 = gce + (size_t)(c + 2) * 32;
            cp16(d + T_A, A + g2); cp16(d + T_A + 16, A + g2 + 8);
            cp16(d + T_B, B + g2); cp16(d + T_B + 16, B + g2 + 8);
        }
        cp_commit();
        uint32_t stg = s0 + (c % 3) * STG;
#pragma unroll
        for (int kk = 0; kk < 2; kk++) {
            uint32_t af[4][4], bfr[4][2];
#pragma unroll
            for (int mt = 0; mt < 4; mt++)
                ldsm4(af[mt], stg + T_A + (wm * 64 + mt * 16 + (l & 15)) * STR + kk * 32 + (l >> 4) * 16);
#pragma unroll
            for (int nt = 0; nt < 4; nt++)
                ldsm2(bfr[nt], stg + T_B + (wn * 32 + nt * 8 + (l & 7)) * STR + kk * 32 + ((l >> 3) & 1) * 16);
#pragma unroll
            for (int mt = 0; mt < 4; mt++)
#pragma unroll
                for (int nt = 0; nt < 4; nt++)
                    mma16816(acc[mt][nt], af[mt], bfr[nt]);
        }
    }
    __syncthreads();

    int g = l >> 2, tg = l & 3;
    const float T2 = 22.63f * 22.63f;
    float sqia[8];
#pragma unroll
    for (int mt = 0; mt < 4; mt++)
#pragma unroll
        for (int h = 0; h < 2; h++)
            sqia[mt * 2 + h] = g_sq[b * NPT + iBase + wm * 64 + mt * 16 + g + h * 8];
    const float* sqj = (const float*)(sb + OFF_SQJ);
    int rq[8], rp[8], cm[8];
#pragma unroll
    for (int e = 0; e < 8; e++) { rq[e] = -1; rp[e] = -1; cm[e] = -1; }
#pragma unroll
    for (int mt = 0; mt < 4; mt++)
#pragma unroll
        for (int nt = 0; nt < 4; nt++)
#pragma unroll
            for (int r = 0; r < 4; r++) {
                int rh = r >> 1, rl = r & 1;
                int ro = wm * 64 + mt * 16 + g + rh * 8;
                int co = wn * 32 + nt * 8 + tg * 2 + rl;
                float d2 = sqia[mt * 2 + rh] + sqj[co] - 2.f * acc[mt][nt][r];
                if (d2 < T2) {
                    rq[mt * 2 + rh] = max(rq[mt * 2 + rh], co);
                    if (diag && co < ro) rp[mt * 2 + rh] = max(rp[mt * 2 + rh], co);
                    if (!diag) cm[nt * 2 + rl] = max(cm[nt * 2 + rl], ro);
                }
            }
    int* sQ = (int*)(sb + OFF_MQ);
    int* sP = (int*)(sb + OFF_MP);
    int* sT = (int*)(sb + OFF_MT);
#pragma unroll
    for (int e = 0; e < 8; e++) {
        int v = rq[e];
        v = max(v, __shfl_xor_sync(0xffffffffu, v, 1));
        v = max(v, __shfl_xor_sync(0xffffffffu, v, 2));
        if (tg == 0 && v >= 0) atomicMax(&sQ[wm * 64 + (e >> 1) * 16 + g + (e & 1) * 8], v);
        if (diag) {
            int u = rp[e];
            u = max(u, __shfl_xor_sync(0xffffffffu, u, 1));
            u = max(u, __shfl_xor_sync(0xffffffffu, u, 2));
            if (tg == 0 && u >= 0) atomicMax(&sP[wm * 64 + (e >> 1) * 16 + g + (e & 1) * 8], u);
        } else {
            int w2 = cm[e];
            w2 = max(w2, __shfl_xor_sync(0xffffffffu, w2, 4));
            w2 = max(w2, __shfl_xor_sync(0xffffffffu, w2, 8));
            w2 = max(w2, __shfl_xor_sync(0xffffffffu, w2, 16));
            if (g == 0 && w2 >= 0) atomicMax(&sT[wn * 32 + (e >> 1) * 8 + tg * 2 + (e & 1)], w2);
        }
    }
    __syncthreads();
    if (t < 128) {
        int gr = b * NPT + iBase + t;
        if (sQ[t] >= 0) atomicMax(&g_q[gr], jBase + sQ[t]);
        if (diag) {
            if (sP[t] >= 0) atomicMax(&g_p[gr], iBase + sP[t]);
        } else if (sT[t] >= 0) {
            int gc = b * NPT + jBase + t;
            int C = iBase + sT[t];
            atomicMax(&g_q[gc], C);
            atomicMax(&g_p[gc], C);
        }
    }
}

// ---- software grid barrier (64 co-resident blocks, one-shot counters) ----
__device__ __forceinline__ void gridbar(int i) {
    __syncthreads();
    if (threadIdx.x == 0) {
        __threadfence();
        atomicAdd(&g_barrier[i], 1);
        while (*(volatile int*)&g_barrier[i] < 64) { }
    }
    __syncthreads();
}

// ---- 3: fused count/scan/assign/jump/labels, 64 blocks x 256 ----
__global__ __launch_bounds__(256) void k_label() {
    __shared__ int woff[8];
    int t = threadIdx.x, lane = t & 31, wid = t >> 5, b = blockIdx.x;
    int x = b * 256 + t;
    int pv = g_p[x];
    int isr = (pv < 0);
    // phase 1: per-block root count
    {
        int r = isr;
#pragma unroll
        for (int o = 16; o; o >>= 1) r += __shfl_xor_sync(0xffffffffu, r, o);
        if (lane == 0) woff[wid] = r;
        __syncthreads();
        if (t == 0) {
            int s = 0;
            for (int w = 0; w < 8; w++) s += woff[w];
            __stcg(&g_ccnt[b], s);
        }
    }
    gridbar(0);
    // phase 2: scan by block 0
    if (b == 0 && t == 0) {
        int s = 0;
        for (int i = 0; i < 64; i++) { __stcg(&g_coff[i], s); s += __ldcg(&g_ccnt[i]); }
        g_Rtot = s;
    }
    gridbar(1);
    // phase 3: assign labels + init pointers
    {
        unsigned int bal = __ballot_sync(0xffffffffu, isr);
        int lp = __popc(bal & ((1u << lane) - 1));
        if (lane == 0) woff[wid] = __popc(bal);
        __syncthreads();
        if (t == 0) {
            int s = 0;
            for (int w = 0; w < 8; w++) { int c = woff[w]; woff[w] = s; s += c; }
        }
        __syncthreads();
        if (isr) { __stcg(&g_labval[x], 1 + __ldcg(&g_coff[b]) + woff[wid] + lp); __stcg(&g_ptrA[x], x); }
        else { __stcg(&g_labval[x], 0); __stcg(&g_ptrA[x], (x & ~(NPT - 1)) + pv); }
    }
    gridbar(2);
    // phase 4: 4 x 8-hop pointer jumping (A->B->A->B->A)
#pragma unroll 1
    for (int it = 0; it < 4; it++) {
        if (!(it & 1)) {
            int a = __ldcg(&g_ptrA[x]);
#pragma unroll
            for (int h = 0; h < 7; h++) a = __ldcg(&g_ptrA[a]);
            __stcg(&g_ptrB[x], a);
        } else {
            int a = __ldcg(&g_ptrB[x]);
#pragma unroll
            for (int h = 0; h < 7; h++) a = __ldcg(&g_ptrB[a]);
            __stcg(&g_ptrA[x], a);
        }
        gridbar(3 + it);
    }
    // phase 5: labels[x] = labval[root(q[x])]
    __stcg(&g_labels[x], __ldcg(&g_labval[__ldcg(&g_ptrA[(x & ~(NPT - 1)) + g_q[x]])]));
}

// ---- 4: histogram / unique / stable compaction + MT19937 choice replay ----
__global__ __launch_bounds__(1024) void k_buildrng() {
    __shared__ int wcnt[32], wpre[32], sTot, sWritten;
    int t = threadIdx.x, lane = t & 31, wid = t >> 5;
    for (int i = t; i < NB * (NTOT + 1); i += 1024) (&g_hist[0][0])[i] = 0;
    __syncthreads();
#pragma unroll
    for (int e = 0; e < 16; e++) {
        int x = t * 16 + e;
        atomicAdd(&g_hist[x >> 12][g_labels[x]], 1);
    }
    __syncthreads();
    int R = g_Rtot;
    if (t < NB) {
        int k = 0;
        for (int l = 1; l <= R; l++) if (g_hist[t][l] > 0) { g_map[t][l] = k; k++; }
        g_Kb[t] = k;
    }
    __syncthreads();
    if (t == 0) {
        int s = 0;
        for (int b = 0; b < NB; b++) { g_KbBase[b] = s; s += g_Kb[b]; }
        g_Ktot = s;
    }
    __syncthreads();
    if (t < NB) {
        int b = t, off = 0, k = 0;
        for (int l = 1; l <= R; l++) {
            int c = g_hist[b][l];
            if (c > 0) {
                int slot = g_KbBase[b] + k;
                g_clusM[slot] = c; g_clusB[slot] = b;
                g_clusBase[slot] = b * NPT + off; g_clusL[slot] = l;
                off += c; k++;
            }
        }
    }
    __syncthreads();
    int K = g_Ktot;
    for (int slot = 0; slot < K; slot++) {
        int b = g_clusB[slot], l = g_clusL[slot], cbase = g_clusBase[slot];
        if (t == 0) sWritten = 0;
        __syncthreads();
        for (int chunk = 0; chunk < NPT; chunk += 1024) {
            int j = chunk + t;
            bool m = (g_labels[b * NPT + j] == l);
            unsigned int bal = __ballot_sync(0xffffffffu, m);
            int lp = __popc(bal & ((1u << lane) - 1));
            if (lane == 0) wcnt[wid] = __popc(bal);
            __syncthreads();
            if (t == 0) {
                int s = 0;
                for (int w = 0; w < 32; w++) { wpre[w] = s; s += wcnt[w]; }
                sTot = s;
            }
            __syncthreads();
            if (m) g_members[cbase + sWritten + wpre[wid] + lp] = j;
            __syncthreads();
            if (t == 0) sWritten += sTot;
            __syncthreads();
        }
    }
    __syncthreads();
    if (t == 0) {
        unsigned int key[624];
        unsigned int s = 0u;
        for (int i = 0; i < 624; i++) { key[i] = s; s = 1812433253u * (s ^ (s >> 30)) + (unsigned)i + 1u; }
        int pos = 624;
        for (int slot = 0; slot < K; slot++) {
            int M = g_clusM[slot], b = g_clusB[slot], cbase = g_clusBase[slot];
            if (M <= 1) {
                int gj = b * NPT + g_members[cbase];
                for (int tt = 0; tt < DS; tt++) g_gidx[slot * DS + tt] = gj;
            } else {
                unsigned int rng = (unsigned int)(M - 1), mask = rng;
                mask |= mask >> 1; mask |= mask >> 2; mask |= mask >> 4; mask |= mask >> 8; mask |= mask >> 16;
                for (int tt = 0; tt < DS; tt++) {
                    unsigned int r;
                    do {
                        if (pos == 624) {
                            for (int i = 0; i < 624; i++) {
                                unsigned int y = (key[i] & 0x80000000u) | (key[(i + 1) % 624] & 0x7fffffffu);
                                unsigned int v2 = key[(i + 397) % 624] ^ (y >> 1);
                                key[i] = (y & 1u) ? (v2 ^ 0x9908b0dfu) : v2;
                            }
                            pos = 0;
                        }
                        unsigned int y = key[pos++];
                        y ^= y >> 11; y ^= (y << 7) & 0x9d2c5680u; y ^= (y << 15) & 0xefc60000u; y ^= y >> 18;
                        r = y & mask;
                    } while (r > rng);
                    g_gidx[slot * DS + tt] = b * NPT + g_members[cbase + (int)r];
                }
            }
        }
    }
}

// ---- 5: PointNet-lite classifier + BCE ----
__global__ __launch_bounds__(128) void k_classify(const float* __restrict__ pts,
        const float* __restrict__ W1, const float* __restrict__ b1,
        const float* __restrict__ W2, const float* __restrict__ b2,
        const float* __restrict__ W3, const float* __restrict__ b3,
        float* __restrict__ out) {
    __shared__ float sW1[192], sb1[64], sW3[256], sb3[2];
    __shared__ float sp[240];
    __shared__ float sh1[80 * 64];
    __shared__ float sred[128];
    int t = threadIdx.x;
    for (int i = t; i < 192; i += 128) sW1[i] = W1[i];
    if (t < 64) sb1[t] = b1[t];
    for (int i = t; i < 256; i += 128) sW3[i] = W3[i];
    if (t < 2) sb3[t] = b3[t];
    float rW2[64];
#pragma unroll
    for (int k = 0; k < 64; k++) rW2[k] = W2[k * 128 + t];
    float rb2 = b2[t];
    __syncthreads();
    int K = g_Ktot;
    for (int slot = blockIdx.x; slot < K; slot += gridDim.x) {
        for (int i = t; i < 240; i += 128) {
            int pt = i / 3, f = i - pt * 3;
            sp[i] = pts[(size_t)g_gidx[slot * DS + pt] * 3 + f];
        }
        __syncthreads();
        for (int o = t; o < 80 * 64; o += 128) {
            int pt = o >> 6, c = o & 63;
            float a = sb1[c] + sp[pt * 3] * sW1[c] + sp[pt * 3 + 1] * sW1[64 + c] + sp[pt * 3 + 2] * sW1[128 + c];
            sh1[o] = fmaxf(a, 0.f);
        }
        __syncthreads();
        float m = -3.402823466e38f;
        for (int pt = 0; pt < 80; pt++) {
            const float* h = &sh1[pt * 64];
            float a = rb2;
#pragma unroll
            for (int k = 0; k < 64; k++) a = fmaf(h[k], rW2[k], a);
            m = fmaxf(m, a);
        }
        float gt = fmaxf(m, 0.f);
        sred[t] = gt * sW3[2 * t];
        __syncthreads();
        for (int off = 64; off; off >>= 1) { if (t < off) sred[t] += sred[t + off]; __syncthreads(); }
        float l0 = sred[0] + sb3[0];
        __syncthreads();
        sred[t] = gt * sW3[2 * t + 1];
        __syncthreads();
        for (int off = 64; off; off >>= 1) { if (t < off) sred[t] += sred[t + off]; __syncthreads(); }
        if (t == 0) {
            float l1 = sred[0] + sb3[1];
            float loss = fminf(log1pf(expf(l0 - l1)), 100.f);
            atomicAdd(out, loss / (float)g_Kb[g_clusB[slot]]);
        }
        __syncthreads();
    }
}

extern "C" void kernel_launch(void* const* d_in, const int* in_sizes, int n_in,
                              void* d_out, int out_size) {
    const float* feat = (const float*)d_in[0];
    const float* pts  = (const float*)d_in[1];
    const float* W1 = (const float*)d_in[2];
    const float* b1 = (const float*)d_in[3];
    const float* W2 = (const float*)d_in[4];
    const float* b2 = (const float*)d_in[5];
    const float* W3 = (const float*)d_in[6];
    const float* b3 = (const float*)d_in[7];
    float* out = (float*)d_out;
    static int attr_set = 0;
    if (!attr_set) {
        cudaFuncSetAttribute(k_mma, cudaFuncAttributeMaxDynamicSharedMemorySize, SMEM_DYN);
        attr_set = 1;
    }
    k_cvtsq<<<NTOT * 32 / 256, 256>>>(feat, out);
    k_mma<<<dim3(NTRI, NB), 256, SMEM_DYN>>>();
    k_label<<<64, 256>>>();
    k_buildrng<<<1, 1024>>>();
    k_classify<<<32, 128>>>(pts, W1, b1, W2, b2, W3, b3, out);
}

// round 12
// speedup vs baseline: 1.1604x; 1.1604x over previous
#include <cuda_runtime.h>
#include <cuda_bf16.h>
#include <cstdint>
#include <math.h>

#define NB 4
#define NPT 4096
#define NF 256
#define NTOT (NB*NPT)
#define DS 80
#define NTILE 32
#define NTRI (NTILE*(NTILE+1)/2)
#define NMT (16*624)

__device__ __nv_bfloat16 g_bf[(size_t)NTOT * NF];
__device__ float g_sq[NTOT];
__device__ int g_p[NTOT], g_q[NTOT], g_labval[NTOT];
__device__ int g_ptrA[NTOT], g_ptrB[NTOT], g_labels[NTOT];
__device__ int g_ccnt[64], g_coff[64];
__device__ unsigned int g_mtstream[NMT];
__device__ int g_hist[NB][NTOT + 1];
__device__ int g_map[NB][NTOT + 1];
__device__ int g_members[NTOT];
__device__ int g_clusM[NTOT], g_clusB[NTOT], g_clusBase[NTOT], g_clusL[NTOT];
__device__ int g_Kb[NB], g_KbBase[NB], g_Ktot, g_Rtot;
__device__ int g_gidx[(size_t)NTOT * DS];

__device__ __forceinline__ uint32_t smem_u32(const void* p) {
    uint32_t a;
    asm("{ .reg .u64 t; cvta.to.shared.u64 t, %1; cvt.u32.u64 %0, t; }" : "=r"(a) : "l"(p));
    return a;
}
__device__ __forceinline__ void cp16(uint32_t dst, const void* src) {
    asm volatile("cp.async.ca.shared.global [%0], [%1], 16;" :: "r"(dst), "l"(src));
}
__device__ __forceinline__ void cp_commit() { asm volatile("cp.async.commit_group;"); }
__device__ __forceinline__ void cp_wait1() { asm volatile("cp.async.wait_group 1;"); }
__device__ __forceinline__ void ldsm4(uint32_t* r, uint32_t a) {
    asm volatile("ldmatrix.sync.aligned.m8n8.x4.shared.b16 {%0,%1,%2,%3}, [%4];"
        : "=r"(r[0]), "=r"(r[1]), "=r"(r[2]), "=r"(r[3]) : "r"(a));
}
__device__ __forceinline__ void ldsm2(uint32_t* r, uint32_t a) {
    asm volatile("ldmatrix.sync.aligned.m8n8.x2.shared.b16 {%0,%1}, [%2];"
        : "=r"(r[0]), "=r"(r[1]) : "r"(a));
}
__device__ __forceinline__ void mma16816(float* c, const uint32_t* a, const uint32_t* b) {
    asm volatile("mma.sync.aligned.m16n8k16.row.col.f32.bf16.bf16.f32 "
        "{%0,%1,%2,%3},{%4,%5,%6,%7},{%8,%9},{%0,%1,%2,%3};"
        : "+f"(c[0]), "+f"(c[1]), "+f"(c[2]), "+f"(c[3])
        : "r"(a[0]), "r"(a[1]), "r"(a[2]), "r"(a[3]), "r"(b[0]), "r"(b[1]));
}

#define STR 80
#define STG 20480
#define T_A 0
#define T_B 10240
#define OFF_SQJ 61440
#define OFF_MQ 61952
#define OFF_MP 62464
#define OFF_MT 62976
#define SMEM_DYN 63488

// ---- 1: fused fp32->bf16 convert + sumsq + p/q init; extra block: parallel MT19937 stream ----
__global__ void k_cvtsq(const float* __restrict__ feat, float* __restrict__ out) {
    if (blockIdx.x == 2048) {
        // MT19937 seed 0 + 16 twist generations, tempered stream to global
        __shared__ unsigned int key[624];
        int t = threadIdx.x;
        if (t == 0) {
            unsigned int s = 0u;
            for (int i = 0; i < 624; i++) { key[i] = s; s = 1812433253u * (s ^ (s >> 30)) + (unsigned)i + 1u; }
        }
        __syncthreads();
        for (int gen = 0; gen < 16; gen++) {
            // phase 1: [0,227)
            unsigned int nv = 0; int idx = -1;
            if (t < 227) {
                idx = t;
                unsigned int y = (key[idx] & 0x80000000u) | (key[idx + 1] & 0x7fffffffu);
                nv = key[idx + 397] ^ (y >> 1);
                if (y & 1u) nv ^= 0x9908b0dfu;
            }
            __syncthreads();
            if (idx >= 0) key[idx] = nv;
            __syncthreads();
            // phase 2: [227,454)
            idx = -1;
            if (t < 227) {
                idx = 227 + t;
                unsigned int y = (key[idx] & 0x80000000u) | (key[idx + 1] & 0x7fffffffu);
                nv = key[idx - 227] ^ (y >> 1);
                if (y & 1u) nv ^= 0x9908b0dfu;
            }
            __syncthreads();
            if (idx >= 0) key[idx] = nv;
            __syncthreads();
            // phase 3: [454,623)
            idx = -1;
            if (t < 169) {
                idx = 454 + t;
                unsigned int y = (key[idx] & 0x80000000u) | (key[idx + 1] & 0x7fffffffu);
                nv = key[idx - 227] ^ (y >> 1);
                if (y & 1u) nv ^= 0x9908b0dfu;
            }
            __syncthreads();
            if (idx >= 0) key[idx] = nv;
            __syncthreads();
            // phase 4: i = 623
            if (t == 0) {
                unsigned int y = (key[623] & 0x80000000u) | (key[0] & 0x7fffffffu);
                unsigned int v = key[396] ^ (y >> 1);
                if (y & 1u) v ^= 0x9908b0dfu;
                key[623] = v;
            }
            __syncthreads();
            for (int i = t; i < 624; i += 256) {
                unsigned int y = key[i];
                y ^= y >> 11; y ^= (y << 7) & 0x9d2c5680u; y ^= (y << 15) & 0xefc60000u; y ^= y >> 18;
                g_mtstream[gen * 624 + i] = y;
            }
            __syncthreads();
        }
        return;
    }
    int gt = blockIdx.x * blockDim.x + threadIdx.x;
    if (gt == 0) out[0] = 0.f;
    if (gt < NTOT) { g_p[gt] = -1; g_q[gt] = -1; }
    int w = gt >> 5, lane = gt & 31;
    const float* r = feat + (size_t)w * NF;
    __nv_bfloat16* d = g_bf + (size_t)w * NF;
    float s = 0.f;
#pragma unroll
    for (int t2 = 0; t2 < NF / 32; t2++) {
        float x = r[t2 * 32 + lane];
        s = fmaf(x, x, s);
        d[t2 * 32 + lane] = __float2bfloat16_rn(x);
    }
#pragma unroll
    for (int o = 16; o; o >>= 1) s += __shfl_xor_sync(0xffffffffu, s, o);
    if (lane == 0) g_sq[w] = s;
}

// ---- 2: bf16 HMMA GEMM, 3-stage cp.async, epilogue -> p/q atomicMax ----
__global__ __launch_bounds__(256, 2) void k_mma() {
    extern __shared__ char sb[];
    uint32_t s0 = smem_u32(sb);
    int t = threadIdx.x, wid = t >> 5, l = t & 31;
    int wm = wid >> 2, wn = wid & 3;
    int ti = blockIdx.x, bi = 0;
    while (ti >= NTILE - bi) { ti -= NTILE - bi; bi++; }
    int bj = bi + ti;
    int b = blockIdx.y;
    int iBase = bi * 128, jBase = bj * 128;
    bool diag = (bi == bj);

    if (t < 128) {
        ((float*)(sb + OFF_SQJ))[t] = g_sq[b * NPT + jBase + t];
        ((int*)(sb + OFF_MQ))[t] = -1;
        ((int*)(sb + OFF_MP))[t] = -1;
        ((int*)(sb + OFF_MT))[t] = -1;
    }

    const __nv_bfloat16* A = g_bf + (size_t)(b * NPT + iBase) * NF;
    const __nv_bfloat16* B = g_bf + (size_t)(b * NPT + jBase) * NF;

    float acc[4][4][4];
#pragma unroll
    for (int mt = 0; mt < 4; mt++)
#pragma unroll
        for (int nt = 0; nt < 4; nt++)
#pragma unroll
            for (int r = 0; r < 4; r++) acc[mt][nt][r] = 0.f;

    int row = t >> 1, half = t & 1;
    uint32_t dce = s0 + row * STR + half * 32;
    size_t gce = (size_t)row * NF + half * 16;
    cp16(dce + T_A, A + gce); cp16(dce + T_A + 16, A + gce + 8);
    cp16(dce + T_B, B + gce); cp16(dce + T_B + 16, B + gce + 8);
    cp_commit();
    cp16(dce + STG + T_A, A + gce + 32); cp16(dce + STG + T_A + 16, A + gce + 40);
    cp16(dce + STG + T_B, B + gce + 32); cp16(dce + STG + T_B + 16, B + gce + 40);
    cp_commit();
#pragma unroll 1
    for (int c = 0; c < 8; c++) {
        cp_wait1();
        __syncthreads();
        if (c < 6) {
            uint32_t d = dce + ((c + 2) % 3) * STG;
            size_t g2 = gce + (size_t)(c + 2) * 32;
            cp16(d + T_A, A + g2); cp16(d + T_A + 16, A + g2 + 8);
            cp16(d + T_B, B + g2); cp16(d + T_B + 16, B + g2 + 8);
        }
        cp_commit();
        uint32_t stg = s0 + (c % 3) * STG;
#pragma unroll
        for (int kk = 0; kk < 2; kk++) {
            uint32_t af[4][4], bfr[4][2];
#pragma unroll
            for (int mt = 0; mt < 4; mt++)
                ldsm4(af[mt], stg + T_A + (wm * 64 + mt * 16 + (l & 15)) * STR + kk * 32 + (l >> 4) * 16);
#pragma unroll
            for (int nt = 0; nt < 4; nt++)
                ldsm2(bfr[nt], stg + T_B + (wn * 32 + nt * 8 + (l & 7)) * STR + kk * 32 + ((l >> 3) & 1) * 16);
#pragma unroll
            for (int mt = 0; mt < 4; mt++)
#pragma unroll
                for (int nt = 0; nt < 4; nt++)
                    mma16816(acc[mt][nt], af[mt], bfr[nt]);
        }
    }
    __syncthreads();

    int g = l >> 2, tg = l & 3;
    const float T2 = 22.63f * 22.63f;
    float sqia[8];
#pragma unroll
    for (int mt = 0; mt < 4; mt++)
#pragma unroll
        for (int h = 0; h < 2; h++)
            sqia[mt * 2 + h] = g_sq[b * NPT + iBase + wm * 64 + mt * 16 + g + h * 8];
    const float* sqj = (const float*)(sb + OFF_SQJ);
    int rq[8], rp[8], cm[8];
#pragma unroll
    for (int e = 0; e < 8; e++) { rq[e] = -1; rp[e] = -1; cm[e] = -1; }
#pragma unroll
    for (int mt = 0; mt < 4; mt++)
#pragma unroll
        for (int nt = 0; nt < 4; nt++)
#pragma unroll
            for (int r = 0; r < 4; r++) {
                int rh = r >> 1, rl = r & 1;
                int ro = wm * 64 + mt * 16 + g + rh * 8;
                int co = wn * 32 + nt * 8 + tg * 2 + rl;
                float d2 = sqia[mt * 2 + rh] + sqj[co] - 2.f * acc[mt][nt][r];
                if (d2 < T2) {
                    rq[mt * 2 + rh] = max(rq[mt * 2 + rh], co);
                    if (diag && co < ro) rp[mt * 2 + rh] = max(rp[mt * 2 + rh], co);
                    if (!diag) cm[nt * 2 + rl] = max(cm[nt * 2 + rl], ro);
                }
            }
    int* sQ = (int*)(sb + OFF_MQ);
    int* sP = (int*)(sb + OFF_MP);
    int* sT = (int*)(sb + OFF_MT);
#pragma unroll
    for (int e = 0; e < 8; e++) {
        int v = rq[e];
        v = max(v, __shfl_xor_sync(0xffffffffu, v, 1));
        v = max(v, __shfl_xor_sync(0xffffffffu, v, 2));
        if (tg == 0 && v >= 0) atomicMax(&sQ[wm * 64 + (e >> 1) * 16 + g + (e & 1) * 8], v);
        if (diag) {
            int u = rp[e];
            u = max(u, __shfl_xor_sync(0xffffffffu, u, 1));
            u = max(u, __shfl_xor_sync(0xffffffffu, u, 2));
            if (tg == 0 && u >= 0) atomicMax(&sP[wm * 64 + (e >> 1) * 16 + g + (e & 1) * 8], u);
        } else {
            int w2 = cm[e];
            w2 = max(w2, __shfl_xor_sync(0xffffffffu, w2, 4));
            w2 = max(w2, __shfl_xor_sync(0xffffffffu, w2, 8));
            w2 = max(w2, __shfl_xor_sync(0xffffffffu, w2, 16));
            if (g == 0 && w2 >= 0) atomicMax(&sT[wn * 32 + (e >> 1) * 8 + tg * 2 + (e & 1)], w2);
        }
    }
    __syncthreads();
    if (t < 128) {
        int gr = b * NPT + iBase + t;
        if (sQ[t] >= 0) atomicMax(&g_q[gr], jBase + sQ[t]);
        if (diag) {
            if (sP[t] >= 0) atomicMax(&g_p[gr], iBase + sP[t]);
        } else if (sT[t] >= 0) {
            int gc = b * NPT + jBase + t;
            int C = iBase + sT[t];
            atomicMax(&g_q[gc], C);
            atomicMax(&g_p[gc], C);
        }
    }
}

// ---- 3: root counting / scan / assignment / 8-hop pointer jumping ----
__global__ void k_rcnt() {
    __shared__ int wsum[8];
    int t = threadIdx.x;
    int x = blockIdx.x * 256 + t;
    int r = (g_p[x] < 0) ? 1 : 0;
#pragma unroll
    for (int o = 16; o; o >>= 1) r += __shfl_xor_sync(0xffffffffu, r, o);
    if ((t & 31) == 0) wsum[t >> 5] = r;
    __syncthreads();
    if (t == 0) {
        int s = 0;
        for (int w = 0; w < 8; w++) s += wsum[w];
        g_ccnt[blockIdx.x] = s;
    }
}
__global__ void k_rscan() {
    if (threadIdx.x == 0) {
        int s = 0;
        for (int i = 0; i < 64; i++) { g_coff[i] = s; s += g_ccnt[i]; }
        g_Rtot = s;
    }
}
__global__ void k_assign() {
    __shared__ int woff[8];
    int t = threadIdx.x, lane = t & 31, wid = t >> 5;
    int x = blockIdx.x * 256 + t;
    int pv = g_p[x];
    int isr = (pv < 0);
    unsigned int bal = __ballot_sync(0xffffffffu, isr);
    int lp = __popc(bal & ((1u << lane) - 1));
    if (lane == 0) woff[wid] = __popc(bal);
    __syncthreads();
    if (t == 0) {
        int s = 0;
        for (int w = 0; w < 8; w++) { int c = woff[w]; woff[w] = s; s += c; }
    }
    __syncthreads();
    if (isr) { g_labval[x] = 1 + g_coff[blockIdx.x] + woff[wid] + lp; g_ptrA[x] = x; }
    else { g_labval[x] = 0; g_ptrA[x] = (x & ~(NPT - 1)) + pv; }
}
__global__ void k_jump8(int phase) {
    int x = blockIdx.x * blockDim.x + threadIdx.x;
    if (phase == 0) {
        int a = g_ptrA[x];
#pragma unroll
        for (int h = 0; h < 7; h++) a = g_ptrA[a];
        g_ptrB[x] = a;
    } else {
        int a = g_ptrB[x];
#pragma unroll
        for (int h = 0; h < 7; h++) a = g_ptrB[a];
        g_ptrA[x] = a;
    }
}
__global__ void k_labfin() {
    int x = blockIdx.x * blockDim.x + threadIdx.x;
    g_labels[x] = g_labval[g_ptrA[(x & ~(NPT - 1)) + g_q[x]]];
}

// ---- 4: histogram / unique / stable compaction + stream-based choice replay ----
__global__ __launch_bounds__(1024) void k_buildrng() {
    __shared__ unsigned int sStream[NMT];   // 39KB
    __shared__ int wcnt[32], wpre[32], sTot, sWritten;
    int t = threadIdx.x, lane = t & 31, wid = t >> 5;
    for (int i = t; i < NMT; i += 1024) sStream[i] = g_mtstream[i];
    for (int i = t; i < NB * (NTOT + 1); i += 1024) (&g_hist[0][0])[i] = 0;
    __syncthreads();
#pragma unroll
    for (int e = 0; e < 16; e++) {
        int x = t * 16 + e;
        atomicAdd(&g_hist[x >> 12][g_labels[x]], 1);
    }
    __syncthreads();
    int R = g_Rtot;
    if (t < NB) {
        int k = 0;
        for (int l = 1; l <= R; l++) if (g_hist[t][l] > 0) { g_map[t][l] = k; k++; }
        g_Kb[t] = k;
    }
    __syncthreads();
    if (t == 0) {
        int s = 0;
        for (int b = 0; b < NB; b++) { g_KbBase[b] = s; s += g_Kb[b]; }
        g_Ktot = s;
    }
    __syncthreads();
    if (t < NB) {
        int b = t, off = 0, k = 0;
        for (int l = 1; l <= R; l++) {
            int c = g_hist[b][l];
            if (c > 0) {
                int slot = g_KbBase[b] + k;
                g_clusM[slot] = c; g_clusB[slot] = b;
                g_clusBase[slot] = b * NPT + off; g_clusL[slot] = l;
                off += c; k++;
            }
        }
    }
    __syncthreads();
    int K = g_Ktot;
    for (int slot = 0; slot < K; slot++) {
        int b = g_clusB[slot], l = g_clusL[slot], cbase = g_clusBase[slot];
        if (t == 0) sWritten = 0;
        __syncthreads();
        for (int chunk = 0; chunk < NPT; chunk += 1024) {
            int j = chunk + t;
            bool m = (g_labels[b * NPT + j] == l);
            unsigned int bal = __ballot_sync(0xffffffffu, m);
            int lp = __popc(bal & ((1u << lane) - 1));
            if (lane == 0) wcnt[wid] = __popc(bal);
            __syncthreads();
            if (t == 0) {
                int s = 0;
                for (int w = 0; w < 32; w++) { wpre[w] = s; s += wcnt[w]; }
                sTot = s;
            }
            __syncthreads();
            if (m) g_members[cbase + sWritten + wpre[wid] + lp] = j;
            __syncthreads();
            if (t == 0) sWritten += sTot;
            __syncthreads();
        }
    }
    __syncthreads();
    // serial rejection replay writes accepted INDEX r; gathers done in parallel after
    if (t == 0) {
        int pos = 0;
        for (int slot = 0; slot < K; slot++) {
            int M = g_clusM[slot];
            if (M <= 1) {
                for (int tt = 0; tt < DS; tt++) g_gidx[slot * DS + tt] = 0;
            } else {
                unsigned int rng = (unsigned int)(M - 1), mask = rng;
                mask |= mask >> 1; mask |= mask >> 2; mask |= mask >> 4; mask |= mask >> 8; mask |= mask >> 16;
                for (int tt = 0; tt < DS; tt++) {
                    unsigned int r;
                    do { r = sStream[pos++] & mask; } while (r > rng);
                    g_gidx[slot * DS + tt] = (int)r;
                }
            }
        }
    }
    __syncthreads();
    for (int i = t; i < K * DS; i += 1024) {
        int slot = i / DS;
        int r = g_gidx[i];
        g_gidx[i] = g_clusB[slot] * NPT + g_members[g_clusBase[slot] + r];
    }
}

// ---- 5: PointNet-lite classifier + BCE ----
__global__ __launch_bounds__(128) void k_classify(const float* __restrict__ pts,
        const float* __restrict__ W1, const float* __restrict__ b1,
        const float* __restrict__ W2, const float* __restrict__ b2,
        const float* __restrict__ W3, const float* __restrict__ b3,
        float* __restrict__ out) {
    __shared__ float sW1[192], sb1[64], sW3[256], sb3[2];
    __shared__ float sp[240];
    __shared__ float sh1[80 * 64];
    __shared__ float sred[128];
    int t = threadIdx.x;
    for (int i = t; i < 192; i += 128) sW1[i] = W1[i];
    if (t < 64) sb1[t] = b1[t];
    for (int i = t; i < 256; i += 128) sW3[i] = W3[i];
    if (t < 2) sb3[t] = b3[t];
    float rW2[64];
#pragma unroll
    for (int k = 0; k < 64; k++) rW2[k] = W2[k * 128 + t];
    float rb2 = b2[t];
    __syncthreads();
    int K = g_Ktot;
    for (int slot = blockIdx.x; slot < K; slot += gridDim.x) {
        for (int i = t; i < 240; i += 128) {
            int pt = i / 3, f = i - pt * 3;
            sp[i] = pts[(size_t)g_gidx[slot * DS + pt] * 3 + f];
        }
        __syncthreads();
        for (int o = t; o < 80 * 64; o += 128) {
            int pt = o >> 6, c = o & 63;
            float a = sb1[c] + sp[pt * 3] * sW1[c] + sp[pt * 3 + 1] * sW1[64 + c] + sp[pt * 3 + 2] * sW1[128 + c];
            sh1[o] = fmaxf(a, 0.f);
        }
        __syncthreads();
        float m = -3.402823466e38f;
        for (int pt = 0; pt < 80; pt++) {
            const float* h = &sh1[pt * 64];
            float a = rb2;
#pragma unroll
            for (int k = 0; k < 64; k++) a = fmaf(h[k], rW2[k], a);
            m = fmaxf(m, a);
        }
        float gt = fmaxf(m, 0.f);
        sred[t] = gt * sW3[2 * t];
        __syncthreads();
        for (int off = 64; off; off >>= 1) { if (t < off) sred[t] += sred[t + off]; __syncthreads(); }
        float l0 = sred[0] + sb3[0];
        __syncthreads();
        sred[t] = gt * sW3[2 * t + 1];
        __syncthreads();
        for (int off = 64; off; off >>= 1) { if (t < off) sred[t] += sred[t + off]; __syncthreads(); }
        if (t == 0) {
            float l1 = sred[0] + sb3[1];
            float loss = fminf(log1pf(expf(l0 - l1)), 100.f);
            atomicAdd(out, loss / (float)g_Kb[g_clusB[slot]]);
        }
        __syncthreads();
    }
}

extern "C" void kernel_launch(void* const* d_in, const int* in_sizes, int n_in,
                              void* d_out, int out_size) {
    const float* feat = (const float*)d_in[0];
    const float* pts  = (const float*)d_in[1];
    const float* W1 = (const float*)d_in[2];
    const float* b1 = (const float*)d_in[3];
    const float* W2 = (const float*)d_in[4];
    const float* b2 = (const float*)d_in[5];
    const float* W3 = (const float*)d_in[6];
    const float* b3 = (const float*)d_in[7];
    float* out = (float*)d_out;
    static int attr_set = 0;
    if (!attr_set) {
        cudaFuncSetAttribute(k_mma, cudaFuncAttributeMaxDynamicSharedMemorySize, SMEM_DYN);
        attr_set = 1;
    }
    k_cvtsq<<<2049, 256>>>(feat, out);
    k_mma<<<dim3(NTRI, NB), 256, SMEM_DYN>>>();
    k_rcnt<<<64, 256>>>();
    k_rscan<<<1, 32>>>();
    k_assign<<<64, 256>>>();
    for (int it = 0; it < 4; it++) k_jump8<<<NTOT / 256, 256>>>(it & 1);
    k_labfin<<<NTOT / 256, 256>>>();
    k_buildrng<<<1, 1024>>>();
    k_classify<<<32, 128>>>(pts, W1, b1, W2, b2, W3, b3, out);
}

// round 15
// speedup vs baseline: 1.1829x; 1.0194x over previous
#include <cuda_runtime.h>
#include <cuda_bf16.h>
#include <cstdint>
#include <math.h>

#define NB 4
#define NPT 4096
#define NF 256
#define NTOT (NB*NPT)
#define DS 80
#define NTILE 32
#define NTRI (NTILE*(NTILE+1)/2)
#define NMT (16*624)

__device__ __nv_bfloat16 g_bf[(size_t)NTOT * NF];
__device__ float g_sq[NTOT];
__device__ int g_p[NTOT], g_q[NTOT], g_labval[NTOT];
__device__ int g_ptrA[NTOT], g_ptrB[NTOT], g_labels[NTOT];
__device__ int g_ccnt[64];
__device__ unsigned int g_mtstream[NMT];
__device__ int g_hist[NB][NTOT + 1];
__device__ int g_map[NB][NTOT + 1];
__device__ int g_members[NTOT];
__device__ int g_clusM[NTOT], g_clusB[NTOT], g_clusBase[NTOT], g_clusL[NTOT];
__device__ int g_Kb[NB], g_KbBase[NB], g_Ktot;
__device__ int g_gidx[(size_t)NTOT * DS];

__device__ __forceinline__ uint32_t smem_u32(const void* p) {
    uint32_t a;
    asm("{ .reg .u64 t; cvta.to.shared.u64 t, %1; cvt.u32.u64 %0, t; }" : "=r"(a) : "l"(p));
    return a;
}
__device__ __forceinline__ void cp16(uint32_t dst, const void* src) {
    asm volatile("cp.async.ca.shared.global [%0], [%1], 16;" :: "r"(dst), "l"(src));
}
__device__ __forceinline__ void cp_commit() { asm volatile("cp.async.commit_group;"); }
__device__ __forceinline__ void cp_wait1() { asm volatile("cp.async.wait_group 1;"); }
__device__ __forceinline__ void ldsm4(uint32_t* r, uint32_t a) {
    asm volatile("ldmatrix.sync.aligned.m8n8.x4.shared.b16 {%0,%1,%2,%3}, [%4];"
        : "=r"(r[0]), "=r"(r[1]), "=r"(r[2]), "=r"(r[3]) : "r"(a));
}
__device__ __forceinline__ void ldsm2(uint32_t* r, uint32_t a) {
    asm volatile("ldmatrix.sync.aligned.m8n8.x2.shared.b16 {%0,%1}, [%2];"
        : "=r"(r[0]), "=r"(r[1]) : "r"(a));
}
__device__ __forceinline__ void mma16816(float* c, const uint32_t* a, const uint32_t* b) {
    asm volatile("mma.sync.aligned.m16n8k16.row.col.f32.bf16.bf16.f32 "
        "{%0,%1,%2,%3},{%4,%5,%6,%7},{%8,%9},{%0,%1,%2,%3};"
        : "+f"(c[0]), "+f"(c[1]), "+f"(c[2]), "+f"(c[3])
        : "r"(a[0]), "r"(a[1]), "r"(a[2]), "r"(a[3]), "r"(b[0]), "r"(b[1]));
}

#define STR 80
#define STG 20480
#define T_A 0
#define T_B 10240
#define OFF_SQJ 61440
#define OFF_MQ 61952
#define OFF_MP 62464
#define OFF_MT 62976
#define SMEM_DYN 63488

// ---- 1: fused fp32->bf16 convert + sumsq + p/q init; extra block: parallel MT19937 stream ----
__global__ void k_cvtsq(const float* __restrict__ feat, float* __restrict__ out) {
    if (blockIdx.x == 2048) {
        __shared__ unsigned int key[624];
        int t = threadIdx.x;
        if (t == 0) {
            unsigned int s = 0u;
            for (int i = 0; i < 624; i++) { key[i] = s; s = 1812433253u * (s ^ (s >> 30)) + (unsigned)i + 1u; }
        }
        __syncthreads();
        for (int gen = 0; gen < 16; gen++) {
            unsigned int nv = 0; int idx = -1;
            if (t < 227) {
                idx = t;
                unsigned int y = (key[idx] & 0x80000000u) | (key[idx + 1] & 0x7fffffffu);
                nv = key[idx + 397] ^ (y >> 1);
                if (y & 1u) nv ^= 0x9908b0dfu;
            }
            __syncthreads();
            if (idx >= 0) key[idx] = nv;
            __syncthreads();
            idx = -1;
            if (t < 227) {
                idx = 227 + t;
                unsigned int y = (key[idx] & 0x80000000u) | (key[idx + 1] & 0x7fffffffu);
                nv = key[idx - 227] ^ (y >> 1);
                if (y & 1u) nv ^= 0x9908b0dfu;
            }
            __syncthreads();
            if (idx >= 0) key[idx] = nv;
            __syncthreads();
            idx = -1;
            if (t < 169) {
                idx = 454 + t;
                unsigned int y = (key[idx] & 0x80000000u) | (key[idx + 1] & 0x7fffffffu);
                nv = key[idx - 227] ^ (y >> 1);
                if (y & 1u) nv ^= 0x9908b0dfu;
            }
            __syncthreads();
            if (idx >= 0) key[idx] = nv;
            __syncthreads();
            if (t == 0) {
                unsigned int y = (key[623] & 0x80000000u) | (key[0] & 0x7fffffffu);
                unsigned int v = key[396] ^ (y >> 1);
                if (y & 1u) v ^= 0x9908b0dfu;
                key[623] = v;
            }
            __syncthreads();
            for (int i = t; i < 624; i += 256) {
                unsigned int y = key[i];
                y ^= y >> 11; y ^= (y << 7) & 0x9d2c5680u; y ^= (y << 15) & 0xefc60000u; y ^= y >> 18;
                g_mtstream[gen * 624 + i] = y;
            }
            __syncthreads();
        }
        return;
    }
    int gt = blockIdx.x * blockDim.x + threadIdx.x;
    if (gt == 0) out[0] = 0.f;
    if (gt < NTOT) { g_p[gt] = -1; g_q[gt] = -1; }
    int w = gt >> 5, lane = gt & 31;
    const float* r = feat + (size_t)w * NF;
    __nv_bfloat16* d = g_bf + (size_t)w * NF;
    float s = 0.f;
#pragma unroll
    for (int t2 = 0; t2 < NF / 32; t2++) {
        float x = r[t2 * 32 + lane];
        s = fmaf(x, x, s);
        d[t2 * 32 + lane] = __float2bfloat16_rn(x);
    }
#pragma unroll
    for (int o = 16; o; o >>= 1) s += __shfl_xor_sync(0xffffffffu, s, o);
    if (lane == 0) g_sq[w] = s;
}

// ---- 2: bf16 HMMA GEMM, 3-stage cp.async, epilogue -> p/q atomicMax ----
__global__ __launch_bounds__(256, 2) void k_mma() {
    extern __shared__ char sb[];
    uint32_t s0 = smem_u32(sb);
    int t = threadIdx.x, wid = t >> 5, l = t & 31;
    int wm = wid >> 2, wn = wid & 3;
    int ti = blockIdx.x, bi = 0;
    while (ti >= NTILE - bi) { ti -= NTILE - bi; bi++; }
    int bj = bi + ti;
    int b = blockIdx.y;
    int iBase = bi * 128, jBase = bj * 128;
    bool diag = (bi == bj);

    if (t < 128) {
        ((float*)(sb + OFF_SQJ))[t] = g_sq[b * NPT + jBase + t];
        ((int*)(sb + OFF_MQ))[t] = -1;
        ((int*)(sb + OFF_MP))[t] = -1;
        ((int*)(sb + OFF_MT))[t] = -1;
    }

    const __nv_bfloat16* A = g_bf + (size_t)(b * NPT + iBase) * NF;
    const __nv_bfloat16* B = g_bf + (size_t)(b * NPT + jBase) * NF;

    float acc[4][4][4];
#pragma unroll
    for (int mt = 0; mt < 4; mt++)
#pragma unroll
        for (int nt = 0; nt < 4; nt++)
#pragma unroll
            for (int r = 0; r < 4; r++) acc[mt][nt][r] = 0.f;

    int row = t >> 1, half = t & 1;
    uint32_t dce = s0 + row * STR + half * 32;
    size_t gce = (size_t)row * NF + half * 16;
    cp16(dce + T_A, A + gce); cp16(dce + T_A + 16, A + gce + 8);
    cp16(dce + T_B, B + gce); cp16(dce + T_B + 16, B + gce + 8);
    cp_commit();
    cp16(dce + STG + T_A, A + gce + 32); cp16(dce + STG + T_A + 16, A + gce + 40);
    cp16(dce + STG + T_B, B + gce + 32); cp16(dce + STG + T_B + 16, B + gce + 40);
    cp_commit();
#pragma unroll 1
    for (int c = 0; c < 8; c++) {
        cp_wait1();
        __syncthreads();
        if (c < 6) {
            uint32_t d = dce + ((c + 2) % 3) * STG;
            size_t g2 = gce + (size_t)(c + 2) * 32;
            cp16(d + T_A, A + g2); cp16(d + T_A + 16, A + g2 + 8);
            cp16(d + T_B, B + g2); cp16(d + T_B + 16, B + g2 + 8);
        }
        cp_commit();
        uint32_t stg = s0 + (c % 3) * STG;
#pragma unroll
        for (int kk = 0; kk < 2; kk++) {
            uint32_t af[4][4], bfr[4][2];
#pragma unroll
            for (int mt = 0; mt < 4; mt++)
                ldsm4(af[mt], stg + T_A + (wm * 64 + mt * 16 + (l & 15)) * STR + kk * 32 + (l >> 4) * 16);
#pragma unroll
            for (int nt = 0; nt < 4; nt++)
                ldsm2(bfr[nt], stg + T_B + (wn * 32 + nt * 8 + (l & 7)) * STR + kk * 32 + ((l >> 3) & 1) * 16);
#pragma unroll
            for (int mt = 0; mt < 4; mt++)
#pragma unroll
                for (int nt = 0; nt < 4; nt++)
                    mma16816(acc[mt][nt], af[mt], bfr[nt]);
        }
    }
    __syncthreads();

    int g = l >> 2, tg = l & 3;
    const float T2 = 22.63f * 22.63f;
    float sqia[8];
#pragma unroll
    for (int mt = 0; mt < 4; mt++)
#pragma unroll
        for (int h = 0; h < 2; h++)
            sqia[mt * 2 + h] = g_sq[b * NPT + iBase + wm * 64 + mt * 16 + g + h * 8];
    const float* sqj = (const float*)(sb + OFF_SQJ);
    int rq[8], rp[8], cm[8];
#pragma unroll
    for (int e = 0; e < 8; e++) { rq[e] = -1; rp[e] = -1; cm[e] = -1; }
#pragma unroll
    for (int mt = 0; mt < 4; mt++)
#pragma unroll
        for (int nt = 0; nt < 4; nt++)
#pragma unroll
            for (int r = 0; r < 4; r++) {
                int rh = r >> 1, rl = r & 1;
                int ro = wm * 64 + mt * 16 + g + rh * 8;
                int co = wn * 32 + nt * 8 + tg * 2 + rl;
                float d2 = sqia[mt * 2 + rh] + sqj[co] - 2.f * acc[mt][nt][r];
                if (d2 < T2) {
                    rq[mt * 2 + rh] = max(rq[mt * 2 + rh], co);
                    if (diag && co < ro) rp[mt * 2 + rh] = max(rp[mt * 2 + rh], co);
                    if (!diag) cm[nt * 2 + rl] = max(cm[nt * 2 + rl], ro);
                }
            }
    int* sQ = (int*)(sb + OFF_MQ);
    int* sP = (int*)(sb + OFF_MP);
    int* sT = (int*)(sb + OFF_MT);
#pragma unroll
    for (int e = 0; e < 8; e++) {
        int v = rq[e];
        v = max(v, __shfl_xor_sync(0xffffffffu, v, 1));
        v = max(v, __shfl_xor_sync(0xffffffffu, v, 2));
        if (tg == 0 && v >= 0) atomicMax(&sQ[wm * 64 + (e >> 1) * 16 + g + (e & 1) * 8], v);
        if (diag) {
            int u = rp[e];
            u = max(u, __shfl_xor_sync(0xffffffffu, u, 1));
            u = max(u, __shfl_xor_sync(0xffffffffu, u, 2));
            if (tg == 0 && u >= 0) atomicMax(&sP[wm * 64 + (e >> 1) * 16 + g + (e & 1) * 8], u);
        } else {
            int w2 = cm[e];
            w2 = max(w2, __shfl_xor_sync(0xffffffffu, w2, 4));
            w2 = max(w2, __shfl_xor_sync(0xffffffffu, w2, 8));
            w2 = max(w2, __shfl_xor_sync(0xffffffffu, w2, 16));
            if (g == 0 && w2 >= 0) atomicMax(&sT[wn * 32 + (e >> 1) * 8 + tg * 2 + (e & 1)], w2);
        }
    }
    __syncthreads();
    if (t < 128) {
        int gr = b * NPT + iBase + t;
        if (sQ[t] >= 0) atomicMax(&g_q[gr], jBase + sQ[t]);
        if (diag) {
            if (sP[t] >= 0) atomicMax(&g_p[gr], iBase + sP[t]);
        } else if (sT[t] >= 0) {
            int gc = b * NPT + jBase + t;
            int C = iBase + sT[t];
            atomicMax(&g_q[gc], C);
            atomicMax(&g_p[gc], C);
        }
    }
}

// ---- 3: root counting / assign (self-prefix) / 16-hop pointer jumping ----
__global__ void k_rcnt() {
    __shared__ int wsum[8];
    int t = threadIdx.x;
    int x = blockIdx.x * 256 + t;
    int r = (g_p[x] < 0) ? 1 : 0;
#pragma unroll
    for (int o = 16; o; o >>= 1) r += __shfl_xor_sync(0xffffffffu, r, o);
    if ((t & 31) == 0) wsum[t >> 5] = r;
    __syncthreads();
    if (t == 0) {
        int s = 0;
        for (int w = 0; w < 8; w++) s += wsum[w];
        g_ccnt[blockIdx.x] = s;
    }
}
__global__ void k_assign() {
    __shared__ int woff[8];
    __shared__ int sPre;
    int t = threadIdx.x, lane = t & 31, wid = t >> 5;
    int x = blockIdx.x * 256 + t;
    int pv = g_p[x];
    int isr = (pv < 0);
    if (t == 0) {
        int s = 0;
        for (int i = 0; i < blockIdx.x; i++) s += g_ccnt[i];
        sPre = s;
    }
    unsigned int bal = __ballot_sync(0xffffffffu, isr);
    int lp = __popc(bal & ((1u << lane) - 1));
    if (lane == 0) woff[wid] = __popc(bal);
    __syncthreads();
    if (t == 0) {
        int s = 0;
        for (int w = 0; w < 8; w++) { int c = woff[w]; woff[w] = s; s += c; }
    }
    __syncthreads();
    if (isr) { g_labval[x] = 1 + sPre + woff[wid] + lp; g_ptrA[x] = x; }
    else { g_labval[x] = 0; g_ptrA[x] = (x & ~(NPT - 1)) + pv; }
}
__global__ void k_jump16(int phase) {
    int x = blockIdx.x * blockDim.x + threadIdx.x;
    if (phase == 0) {
        int a = g_ptrA[x];
#pragma unroll
        for (int h = 0; h < 15; h++) a = g_ptrA[a];
        g_ptrB[x] = a;
    } else {
        int a = g_ptrB[x];
#pragma unroll
        for (int h = 0; h < 15; h++) a = g_ptrB[a];
        g_ptrA[x] = a;
    }
}
__global__ void k_labfin() {
    int x = blockIdx.x * blockDim.x + threadIdx.x;
    g_labels[x] = g_labval[g_ptrB[(x & ~(NPT - 1)) + g_q[x]]];
}

// ---- 4: histogram / unique / stable compaction + stream-based choice replay ----
__global__ __launch_bounds__(1024) void k_buildrng() {
    __shared__ unsigned int sStream[NMT];
    __shared__ int wcnt[32], wpre[32], sTot, sWritten, sR;
    int t = threadIdx.x, lane = t & 31, wid = t >> 5;
    if (t == 0) {
        int s = 0;
        for (int i = 0; i < 64; i++) s += g_ccnt[i];
        sR = s;
    }
    for (int i = t; i < NMT; i += 1024) sStream[i] = g_mtstream[i];
    for (int i = t; i < NB * (NTOT + 1); i += 1024) (&g_hist[0][0])[i] = 0;
    __syncthreads();
#pragma unroll
    for (int e = 0; e < 16; e++) {
        int x = t * 16 + e;
        atomicAdd(&g_hist[x >> 12][g_labels[x]], 1);
    }
    __syncthreads();
    int R = sR;
    if (t < NB) {
        int k = 0;
        for (int l = 1; l <= R; l++) if (g_hist[t][l] > 0) { g_map[t][l] = k; k++; }
        g_Kb[t] = k;
    }
    __syncthreads();
    if (t == 0) {
        int s = 0;
        for (int b = 0; b < NB; b++) { g_KbBase[b] = s; s += g_Kb[b]; }
        g_Ktot = s;
    }
    __syncthreads();
    if (t < NB) {
        int b = t, off = 0, k = 0;
        for (int l = 1; l <= R; l++) {
            int c = g_hist[b][l];
            if (c > 0) {
                int slot = g_KbBase[b] + k;
                g_clusM[slot] = c; g_clusB[slot] = b;
                g_clusBase[slot] = b * NPT + off; g_clusL[slot] = l;
                off += c; k++;
            }
        }
    }
    __syncthreads();
    int K = g_Ktot;
    for (int slot = 0; slot < K; slot++) {
        int b = g_clusB[slot], l = g_clusL[slot], cbase = g_clusBase[slot];
        if (t == 0) sWritten = 0;
        __syncthreads();
        for (int chunk = 0; chunk < NPT; chunk += 1024) {
            int j = chunk + t;
            bool m = (g_labels[b * NPT + j] == l);
            unsigned int bal = __ballot_sync(0xffffffffu, m);
            int lp = __popc(bal & ((1u << lane) - 1));
            if (lane == 0) wcnt[wid] = __popc(bal);
            __syncthreads();
            if (t == 0) {
                int s = 0;
                for (int w = 0; w < 32; w++) { wpre[w] = s; s += wcnt[w]; }
                sTot = s;
            }
            __syncthreads();
            if (m) g_members[cbase + sWritten + wpre[wid] + lp] = j;
            __syncthreads();
            if (t == 0) sWritten += sTot;
            __syncthreads();
        }
    }
    __syncthreads();
    if (t == 0) {
        int pos = 0;
        for (int slot = 0; slot < K; slot++) {
            int M = g_clusM[slot];
            if (M <= 1) {
                for (int tt = 0; tt < DS; tt++) g_gidx[slot * DS + tt] = 0;
            } else {
                unsigned int rng = (unsigned int)(M - 1), mask = rng;
                mask |= mask >> 1; mask |= mask >> 2; mask |= mask >> 4; mask |= mask >> 8; mask |= mask >> 16;
                for (int tt = 0; tt < DS; tt++) {
                    unsigned int r;
                    do { r = sStream[pos++] & mask; } while (r > rng);
                    g_gidx[slot * DS + tt] = (int)r;
                }
            }
        }
    }
    __syncthreads();
    for (int i = t; i < K * DS; i += 1024) {
        int slot = i / DS;
        int r = g_gidx[i];
        g_gidx[i] = g_clusB[slot] * NPT + g_members[g_clusBase[slot] + r];
    }
}

// ---- 5: PointNet-lite classifier + BCE ----
__global__ __launch_bounds__(128) void k_classify(const float* __restrict__ pts,
        const float* __restrict__ W1, const float* __restrict__ b1,
        const float* __restrict__ W2, const float* __restrict__ b2,
        const float* __restrict__ W3, const float* __restrict__ b3,
        float* __restrict__ out) {
    __shared__ float sW1[192], sb1[64], sW3[256], sb3[2];
    __shared__ float sp[240];
    __shared__ float sh1[80 * 64];
    __shared__ float sred[128];
    int t = threadIdx.x;
    for (int i = t; i < 192; i += 128) sW1[i] = W1[i];
    if (t < 64) sb1[t] = b1[t];
    for (int i = t; i < 256; i += 128) sW3[i] = W3[i];
    if (t < 2) sb3[t] = b3[t];
    float rW2[64];
#pragma unroll
    for (int k = 0; k < 64; k++) rW2[k] = W2[k * 128 + t];
    float rb2 = b2[t];
    __syncthreads();
    int K = g_Ktot;
    for (int slot = blockIdx.x; slot < K; slot += gridDim.x) {
        for (int i = t; i < 240; i += 128) {
            int pt = i / 3, f = i - pt * 3;
            sp[i] = pts[(size_t)g_gidx[slot * DS + pt] * 3 + f];
        }
        __syncthreads();
        for (int o = t; o < 80 * 64; o += 128) {
            int pt = o >> 6, c = o & 63;
            float a = sb1[c] + sp[pt * 3] * sW1[c] + sp[pt * 3 + 1] * sW1[64 + c] + sp[pt * 3 + 2] * sW1[128 + c];
            sh1[o] = fmaxf(a, 0.f);
        }
        __syncthreads();
        float m = -3.402823466e38f;
        for (int pt = 0; pt < 80; pt++) {
            const float* h = &sh1[pt * 64];
            float a = rb2;
#pragma unroll
            for (int k = 0; k < 64; k++) a = fmaf(h[k], rW2[k], a);
            m = fmaxf(m, a);
        }
        float gt = fmaxf(m, 0.f);
        sred[t] = gt * sW3[2 * t];
        __syncthreads();
        for (int off = 64; off; off >>= 1) { if (t < off) sred[t] += sred[t + off]; __syncthreads(); }
        float l0 = sred[0] + sb3[0];
        __syncthreads();
        sred[t] = gt * sW3[2 * t + 1];
        __syncthreads();
        for (int off = 64; off; off >>= 1) { if (t < off) sred[t] += sred[t + off]; __syncthreads(); }
        if (t == 0) {
            float l1 = sred[0] + sb3[1];
            float loss = fminf(log1pf(expf(l0 - l1)), 100.f);
            atomicAdd(out, loss / (float)g_Kb[g_clusB[slot]]);
        }
        __syncthreads();
    }
}

extern "C" void kernel_launch(void* const* d_in, const int* in_sizes, int n_in,
                              void* d_out, int out_size) {
    const float* feat = (const float*)d_in[0];
    const float* pts  = (const float*)d_in[1];
    const float* W1 = (const float*)d_in[2];
    const float* b1 = (const float*)d_in[3];
    const float* W2 = (const float*)d_in[4];
    const float* b2 = (const float*)d_in[5];
    const float* W3 = (const float*)d_in[6];
    const float* b3 = (const float*)d_in[7];
    float* out = (float*)d_out;
    static int attr_set = 0;
    if (!attr_set) {
        cudaFuncSetAttribute(k_mma, cudaFuncAttributeMaxDynamicSharedMemorySize, SMEM_DYN);
        attr_set = 1;
    }
    k_cvtsq<<<2049, 256>>>(feat, out);
    k_mma<<<dim3(NTRI, NB), 256, SMEM_DYN>>>();
    k_rcnt<<<64, 256>>>();
    k_assign<<<64, 256>>>();
    k_jump16<<<NTOT / 256, 256>>>(0);
    k_jump16<<<NTOT / 256, 256>>>(1);
    k_jump16<<<NTOT / 256, 256>>>(0);
    k_labfin<<<NTOT / 256, 256>>>();
    k_buildrng<<<1, 1024>>>();
    k_classify<<<32, 128>>>(pts, W1, b1, W2, b2, W3, b3, out);
}

// round 16
// speedup vs baseline: 1.8508x; 1.5646x over previous
#include <cuda_runtime.h>
#include <cuda_bf16.h>
#include <cstdint>
#include <math.h>

#define NB 4
#define NPT 4096
#define NF 256
#define NTOT (NB*NPT)
#define DS 80
#define NTILE 32
#define NMT (16*624)

__device__ __nv_bfloat16 g_bf[(size_t)NTOT * NF];
__device__ float g_sq[NTOT];
__device__ int g_p[NTOT], g_q[NTOT], g_labval[NTOT];
__device__ int g_ptrA[NTOT], g_ptrB[NTOT], g_labels[NTOT];
__device__ int g_ccnt[64];
__device__ unsigned int g_mtstream[NMT];
__device__ int g_hist[NB][NTOT + 1];
__device__ int g_map[NB][NTOT + 1];
__device__ int g_members[NTOT];
__device__ int g_clusM[NTOT], g_clusB[NTOT], g_clusBase[NTOT], g_clusL[NTOT];
__device__ int g_Kb[NB], g_KbBase[NB], g_Ktot;
__device__ int g_gidx[(size_t)NTOT * DS];

__device__ __forceinline__ uint32_t smem_u32(const void* p) {
    uint32_t a;
    asm("{ .reg .u64 t; cvta.to.shared.u64 t, %1; cvt.u32.u64 %0, t; }" : "=r"(a) : "l"(p));
    return a;
}
__device__ __forceinline__ void cp16(uint32_t dst, const void* src) {
    asm volatile("cp.async.ca.shared.global [%0], [%1], 16;" :: "r"(dst), "l"(src));
}
__device__ __forceinline__ void cp_commit() { asm volatile("cp.async.commit_group;"); }
__device__ __forceinline__ void cp_wait1() { asm volatile("cp.async.wait_group 1;"); }
__device__ __forceinline__ void ldsm4(uint32_t* r, uint32_t a) {
    asm volatile("ldmatrix.sync.aligned.m8n8.x4.shared.b16 {%0,%1,%2,%3}, [%4];"
        : "=r"(r[0]), "=r"(r[1]), "=r"(r[2]), "=r"(r[3]) : "r"(a));
}
__device__ __forceinline__ void ldsm2(uint32_t* r, uint32_t a) {
    asm volatile("ldmatrix.sync.aligned.m8n8.x2.shared.b16 {%0,%1}, [%2];"
        : "=r"(r[0]), "=r"(r[1]) : "r"(a));
}
__device__ __forceinline__ void mma16816(float* c, const uint32_t* a, const uint32_t* b) {
    asm volatile("mma.sync.aligned.m16n8k16.row.col.f32.bf16.bf16.f32 "
        "{%0,%1,%2,%3},{%4,%5,%6,%7},{%8,%9},{%0,%1,%2,%3};"
        : "+f"(c[0]), "+f"(c[1]), "+f"(c[2]), "+f"(c[3])
        : "r"(a[0]), "r"(a[1]), "r"(a[2]), "r"(a[3]), "r"(b[0]), "r"(b[1]));
}

#define STR 80
#define STG 20480
#define T_A 0
#define T_B 10240
#define OFF_SQJ 61440
#define OFF_MQ 61952
#define OFF_MP 62464
#define SMEM_DYN 63488

// ---- 1: fused fp32->bf16 convert + sumsq; extra block: parallel MT19937 stream ----
__global__ void k_cvtsq(const float* __restrict__ feat, float* __restrict__ out) {
    if (blockIdx.x == 2048) {
        __shared__ unsigned int key[624];
        int t = threadIdx.x;
        if (t == 0) {
            unsigned int s = 0u;
            for (int i = 0; i < 624; i++) { key[i] = s; s = 1812433253u * (s ^ (s >> 30)) + (unsigned)i + 1u; }
        }
        __syncthreads();
        for (int gen = 0; gen < 16; gen++) {
            unsigned int nv = 0; int idx = -1;
            if (t < 227) {
                idx = t;
                unsigned int y = (key[idx] & 0x80000000u) | (key[idx + 1] & 0x7fffffffu);
                nv = key[idx + 397] ^ (y >> 1);
                if (y & 1u) nv ^= 0x9908b0dfu;
            }
            __syncthreads();
            if (idx >= 0) key[idx] = nv;
            __syncthreads();
            idx = -1;
            if (t < 227) {
                idx = 227 + t;
                unsigned int y = (key[idx] & 0x80000000u) | (key[idx + 1] & 0x7fffffffu);
                nv = key[idx - 227] ^ (y >> 1);
                if (y & 1u) nv ^= 0x9908b0dfu;
            }
            __syncthreads();
            if (idx >= 0) key[idx] = nv;
            __syncthreads();
            idx = -1;
            if (t < 169) {
                idx = 454 + t;
                unsigned int y = (key[idx] & 0x80000000u) | (key[idx + 1] & 0x7fffffffu);
                nv = key[idx - 227] ^ (y >> 1);
                if (y & 1u) nv ^= 0x9908b0dfu;
            }
            __syncthreads();
            if (idx >= 0) key[idx] = nv;
            __syncthreads();
            if (t == 0) {
                unsigned int y = (key[623] & 0x80000000u) | (key[0] & 0x7fffffffu);
                unsigned int v = key[396] ^ (y >> 1);
                if (y & 1u) v ^= 0x9908b0dfu;
                key[623] = v;
            }
            __syncthreads();
            for (int i = t; i < 624; i += 256) {
                unsigned int y = key[i];
                y ^= y >> 11; y ^= (y << 7) & 0x9d2c5680u; y ^= (y << 15) & 0xefc60000u; y ^= y >> 18;
                g_mtstream[gen * 624 + i] = y;
            }
            __syncthreads();
        }
        return;
    }
    int gt = blockIdx.x * blockDim.x + threadIdx.x;
    if (gt == 0) out[0] = 0.f;
    int w = gt >> 5, lane = gt & 31;
    const float* r = feat + (size_t)w * NF;
    __nv_bfloat16* d = g_bf + (size_t)w * NF;
    float s = 0.f;
#pragma unroll
    for (int t2 = 0; t2 < NF / 32; t2++) {
        float x = r[t2 * 32 + lane];
        s = fmaf(x, x, s);
        d[t2 * 32 + lane] = __float2bfloat16_rn(x);
    }
#pragma unroll
    for (int o = 16; o; o >>= 1) s += __shfl_xor_sync(0xffffffffu, s, o);
    if (lane == 0) g_sq[w] = s;
}

// ---- 2: descending-scan bf16 HMMA with early exit: per row-block, find q and p ----
__global__ __launch_bounds__(256, 1) void k_scan() {
    extern __shared__ char sb[];
    uint32_t s0 = smem_u32(sb);
    __shared__ int sNQ, sNP;
    int t = threadIdx.x, wid = t >> 5, l = t & 31;
    int wm = wid >> 2, wn = wid & 3;
    int bi = blockIdx.x, b = blockIdx.y;
    int iBase = bi * 128;
    int* sQ = (int*)(sb + OFF_MQ);
    int* sP = (int*)(sb + OFF_MP);
    if (t < 128) { sQ[t] = -1; sP[t] = -1; }

    const __nv_bfloat16* A = g_bf + (size_t)(b * NPT + iBase) * NF;
    int g = l >> 2, tg = l & 3;
    float sqia[8];
#pragma unroll
    for (int e = 0; e < 8; e++)
        sqia[e] = g_sq[b * NPT + iBase + wm * 64 + (e >> 1) * 16 + g + (e & 1) * 8];

    int row = t >> 1, half = t & 1;
    uint32_t dce = s0 + row * STR + half * 32;
    size_t gce = (size_t)row * NF + half * 16;
    const float T2 = 22.63f * 22.63f;

    int bj = NTILE - 1;
    while (bj >= 0) {
        // exact completion check
        __syncthreads();
        if (t == 0) { sNQ = 0; sNP = 0; }
        __syncthreads();
        if (t < 128) {
            if (sQ[t] < 0) atomicAdd(&sNQ, 1);
            if (sP[t] < 0) atomicAdd(&sNP, 1);
        }
        __syncthreads();
        if (sNQ == 0 && sNP == 0) break;
        if (sNQ == 0 && bj > bi) { bj = bi; continue; }  // tiles above diag can't supply p

        int jBase = bj * 128;
        bool diag = (bi == bj), below = (bj < bi);
        const __nv_bfloat16* B = g_bf + (size_t)(b * NPT + jBase) * NF;
        if (t < 128) ((float*)(sb + OFF_SQJ))[t] = g_sq[b * NPT + jBase + t];

        float acc[4][4][4];
#pragma unroll
        for (int mt = 0; mt < 4; mt++)
#pragma unroll
            for (int nt = 0; nt < 4; nt++)
#pragma unroll
                for (int r = 0; r < 4; r++) acc[mt][nt][r] = 0.f;

        cp16(dce + T_A, A + gce); cp16(dce + T_A + 16, A + gce + 8);
        cp16(dce + T_B, B + gce); cp16(dce + T_B + 16, B + gce + 8);
        cp_commit();
        cp16(dce + STG + T_A, A + gce + 32); cp16(dce + STG + T_A + 16, A + gce + 40);
        cp16(dce + STG + T_B, B + gce + 32); cp16(dce + STG + T_B + 16, B + gce + 40);
        cp_commit();
#pragma unroll 1
        for (int c = 0; c < 8; c++) {
            cp_wait1();
            __syncthreads();
            if (c < 6) {
                uint32_t d = dce + ((c + 2) % 3) * STG;
                size_t g2 = gce + (size_t)(c + 2) * 32;
                cp16(d + T_A, A + g2); cp16(d + T_A + 16, A + g2 + 8);
                cp16(d + T_B, B + g2); cp16(d + T_B + 16, B + g2 + 8);
            }
            cp_commit();
            uint32_t stg = s0 + (c % 3) * STG;
#pragma unroll
            for (int kk = 0; kk < 2; kk++) {
                uint32_t af[4][4], bfr[4][2];
#pragma unroll
                for (int mt = 0; mt < 4; mt++)
                    ldsm4(af[mt], stg + T_A + (wm * 64 + mt * 16 + (l & 15)) * STR + kk * 32 + (l >> 4) * 16);
#pragma unroll
                for (int nt = 0; nt < 4; nt++)
                    ldsm2(bfr[nt], stg + T_B + (wn * 32 + nt * 8 + (l & 7)) * STR + kk * 32 + ((l >> 3) & 1) * 16);
#pragma unroll
                for (int mt = 0; mt < 4; mt++)
#pragma unroll
                    for (int nt = 0; nt < 4; nt++)
                        mma16816(acc[mt][nt], af[mt], bfr[nt]);
            }
        }
        __syncthreads();

        // epilogue: threshold -> per-row max col (q) and max col meeting p-rule
        const float* sqj = (const float*)(sb + OFF_SQJ);
        int rq[8], rp[8];
#pragma unroll
        for (int e = 0; e < 8; e++) { rq[e] = -1; rp[e] = -1; }
#pragma unroll
        for (int mt = 0; mt < 4; mt++)
#pragma unroll
            for (int nt = 0; nt < 4; nt++)
#pragma unroll
                for (int r = 0; r < 4; r++) {
                    int rh = r >> 1, rl = r & 1;
                    int ro = wm * 64 + mt * 16 + g + rh * 8;
                    int co = wn * 32 + nt * 8 + tg * 2 + rl;
                    float d2 = sqia[mt * 2 + rh] + sqj[co] - 2.f * acc[mt][nt][r];
                    if (d2 < T2) {
                        rq[mt * 2 + rh] = max(rq[mt * 2 + rh], co);
                        if (below || (diag && co < ro)) rp[mt * 2 + rh] = max(rp[mt * 2 + rh], co);
                    }
                }
#pragma unroll
        for (int e = 0; e < 8; e++) {
            int rl2 = wm * 64 + (e >> 1) * 16 + g + (e & 1) * 8;
            int v = rq[e];
            v = max(v, __shfl_xor_sync(0xffffffffu, v, 1));
            v = max(v, __shfl_xor_sync(0xffffffffu, v, 2));
            if (tg == 0 && v >= 0) atomicMax(&sQ[rl2], jBase + v);
            int u = rp[e];
            u = max(u, __shfl_xor_sync(0xffffffffu, u, 1));
            u = max(u, __shfl_xor_sync(0xffffffffu, u, 2));
            if (tg == 0 && u >= 0) atomicMax(&sP[rl2], jBase + u);
        }
        bj--;
    }
    __syncthreads();
    if (t < 128) {
        int x = b * NPT + iBase + t;
        g_q[x] = sQ[t];
        g_p[x] = sP[t];
    }
}

// ---- 3: root counting / assign (self-prefix) / 16-hop pointer jumping ----
__global__ void k_rcnt() {
    __shared__ int wsum[8];
    int t = threadIdx.x;
    int x = blockIdx.x * 256 + t;
    int r = (g_p[x] < 0) ? 1 : 0;
#pragma unroll
    for (int o = 16; o; o >>= 1) r += __shfl_xor_sync(0xffffffffu, r, o);
    if ((t & 31) == 0) wsum[t >> 5] = r;
    __syncthreads();
    if (t == 0) {
        int s = 0;
        for (int w = 0; w < 8; w++) s += wsum[w];
        g_ccnt[blockIdx.x] = s;
    }
}
__global__ void k_assign() {
    __shared__ int woff[8];
    __shared__ int sPre;
    int t = threadIdx.x, lane = t & 31, wid = t >> 5;
    int x = blockIdx.x * 256 + t;
    int pv = g_p[x];
    int isr = (pv < 0);
    if (t == 0) {
        int s = 0;
        for (int i = 0; i < blockIdx.x; i++) s += g_ccnt[i];
        sPre = s;
    }
    unsigned int bal = __ballot_sync(0xffffffffu, isr);
    int lp = __popc(bal & ((1u << lane) - 1));
    if (lane == 0) woff[wid] = __popc(bal);
    __syncthreads();
    if (t == 0) {
        int s = 0;
        for (int w = 0; w < 8; w++) { int c = woff[w]; woff[w] = s; s += c; }
    }
    __syncthreads();
    if (isr) { g_labval[x] = 1 + sPre + woff[wid] + lp; g_ptrA[x] = x; }
    else { g_labval[x] = 0; g_ptrA[x] = (x & ~(NPT - 1)) + pv; }
}
__global__ void k_jump16(int phase) {
    int x = blockIdx.x * blockDim.x + threadIdx.x;
    if (phase == 0) {
        int a = g_ptrA[x];
#pragma unroll
        for (int h = 0; h < 15; h++) a = g_ptrA[a];
        g_ptrB[x] = a;
    } else {
        int a = g_ptrB[x];
#pragma unroll
        for (int h = 0; h < 15; h++) a = g_ptrB[a];
        g_ptrA[x] = a;
    }
}
__global__ void k_labfin() {
    int x = blockIdx.x * blockDim.x + threadIdx.x;
    g_labels[x] = g_labval[g_ptrB[(x & ~(NPT - 1)) + g_q[x]]];
}

// ---- 4: histogram / unique / stable compaction + stream-based choice replay ----
__global__ __launch_bounds__(1024) void k_buildrng() {
    __shared__ unsigned int sStream[NMT];
    __shared__ int wcnt[32], wpre[32], sTot, sWritten, sR;
    int t = threadIdx.x, lane = t & 31, wid = t >> 5;
    if (t == 0) {
        int s = 0;
        for (int i = 0; i < 64; i++) s += g_ccnt[i];
        sR = s;
    }
    for (int i = t; i < NMT; i += 1024) sStream[i] = g_mtstream[i];
    for (int i = t; i < NB * (NTOT + 1); i += 1024) (&g_hist[0][0])[i] = 0;
    __syncthreads();
#pragma unroll
    for (int e = 0; e < 16; e++) {
        int x = t * 16 + e;
        atomicAdd(&g_hist[x >> 12][g_labels[x]], 1);
    }
    __syncthreads();
    int R = sR;
    if (t < NB) {
        int k = 0;
        for (int l = 1; l <= R; l++) if (g_hist[t][l] > 0) { g_map[t][l] = k; k++; }
        g_Kb[t] = k;
    }
    __syncthreads();
    if (t == 0) {
        int s = 0;
        for (int b = 0; b < NB; b++) { g_KbBase[b] = s; s += g_Kb[b]; }
        g_Ktot = s;
    }
    __syncthreads();
    if (t < NB) {
        int b = t, off = 0, k = 0;
        for (int l = 1; l <= R; l++) {
            int c = g_hist[b][l];
            if (c > 0) {
                int slot = g_KbBase[b] + k;
                g_clusM[slot] = c; g_clusB[slot] = b;
                g_clusBase[slot] = b * NPT + off; g_clusL[slot] = l;
                off += c; k++;
            }
        }
    }
    __syncthreads();
    int K = g_Ktot;
    for (int slot = 0; slot < K; slot++) {
        int b = g_clusB[slot], l = g_clusL[slot], cbase = g_clusBase[slot];
        if (t == 0) sWritten = 0;
        __syncthreads();
        for (int chunk = 0; chunk < NPT; chunk += 1024) {
            int j = chunk + t;
            bool m = (g_labels[b * NPT + j] == l);
            unsigned int bal = __ballot_sync(0xffffffffu, m);
            int lp = __popc(bal & ((1u << lane) - 1));
            if (lane == 0) wcnt[wid] = __popc(bal);
            __syncthreads();
            if (t == 0) {
                int s = 0;
                for (int w = 0; w < 32; w++) { wpre[w] = s; s += wcnt[w]; }
                sTot = s;
            }
            __syncthreads();
            if (m) g_members[cbase + sWritten + wpre[wid] + lp] = j;
            __syncthreads();
            if (t == 0) sWritten += sTot;
            __syncthreads();
        }
    }
    __syncthreads();
    if (t == 0) {
        int pos = 0;
        for (int slot = 0; slot < K; slot++) {
            int M = g_clusM[slot];
            if (M <= 1) {
                for (int tt = 0; tt < DS; tt++) g_gidx[slot * DS + tt] = 0;
            } else {
                unsigned int rng = (unsigned int)(M - 1), mask = rng;
                mask |= mask >> 1; mask |= mask >> 2; mask |= mask >> 4; mask |= mask >> 8; mask |= mask >> 16;
                for (int tt = 0; tt < DS; tt++) {
                    unsigned int r;
                    do { r = sStream[pos++] & mask; } while (r > rng);
                    g_gidx[slot * DS + tt] = (int)r;
                }
            }
        }
    }
    __syncthreads();
    for (int i = t; i < K * DS; i += 1024) {
        int slot = i / DS;
        int r = g_gidx[i];
        g_gidx[i] = g_clusB[slot] * NPT + g_members[g_clusBase[slot] + r];
    }
}

// ---- 5: PointNet-lite classifier + BCE ----
__global__ __launch_bounds__(128) void k_classify(const float* __restrict__ pts,
        const float* __restrict__ W1, const float* __restrict__ b1,
        const float* __restrict__ W2, const float* __restrict__ b2,
        const float* __restrict__ W3, const float* __restrict__ b3,
        float* __restrict__ out) {
    __shared__ float sW1[192], sb1[64], sW3[256], sb3[2];
    __shared__ float sp[240];
    __shared__ float sh1[80 * 64];
    __shared__ float sred[128];
    int t = threadIdx.x;
    for (int i = t; i < 192; i += 128) sW1[i] = W1[i];
    if (t < 64) sb1[t] = b1[t];
    for (int i = t; i < 256; i += 128) sW3[i] = W3[i];
    if (t < 2) sb3[t] = b3[t];
    float rW2[64];
#pragma unroll
    for (int k = 0; k < 64; k++) rW2[k] = W2[k * 128 + t];
    float rb2 = b2[t];
    __syncthreads();
    int K = g_Ktot;
    for (int slot = blockIdx.x; slot < K; slot += gridDim.x) {
        for (int i = t; i < 240; i += 128) {
            int pt = i / 3, f = i - pt * 3;
            sp[i] = pts[(size_t)g_gidx[slot * DS + pt] * 3 + f];
        }
        __syncthreads();
        for (int o = t; o < 80 * 64; o += 128) {
            int pt = o >> 6, c = o & 63;
            float a = sb1[c] + sp[pt * 3] * sW1[c] + sp[pt * 3 + 1] * sW1[64 + c] + sp[pt * 3 + 2] * sW1[128 + c];
            sh1[o] = fmaxf(a, 0.f);
        }
        __syncthreads();
        float m = -3.402823466e38f;
        for (int pt = 0; pt < 80; pt++) {
            const float* h = &sh1[pt * 64];
            float a = rb2;
#pragma unroll
            for (int k = 0; k < 64; k++) a = fmaf(h[k], rW2[k], a);
            m = fmaxf(m, a);
        }
        float gt = fmaxf(m, 0.f);
        sred[t] = gt * sW3[2 * t];
        __syncthreads();
        for (int off = 64; off; off >>= 1) { if (t < off) sred[t] += sred[t + off]; __syncthreads(); }
        float l0 = sred[0] + sb3[0];
        __syncthreads();
        sred[t] = gt * sW3[2 * t + 1];
        __syncthreads();
        for (int off = 64; off; off >>= 1) { if (t < off) sred[t] += sred[t + off]; __syncthreads(); }
        if (t == 0) {
            float l1 = sred[0] + sb3[1];
            float loss = fminf(log1pf(expf(l0 - l1)), 100.f);
            atomicAdd(out, loss / (float)g_Kb[g_clusB[slot]]);
        }
        __syncthreads();
    }
}

extern "C" void kernel_launch(void* const* d_in, const int* in_sizes, int n_in,
                              void* d_out, int out_size) {
    const float* feat = (const float*)d_in[0];
    const float* pts  = (const float*)d_in[1];
    const float* W1 = (const float*)d_in[2];
    const float* b1 = (const float*)d_in[3];
    const float* W2 = (const float*)d_in[4];
    const float* b2 = (const float*)d_in[5];
    const float* W3 = (const float*)d_in[6];
    const float* b3 = (const float*)d_in[7];
    float* out = (float*)d_out;
    static int attr_set = 0;
    if (!attr_set) {
        cudaFuncSetAttribute(k_scan, cudaFuncAttributeMaxDynamicSharedMemorySize, SMEM_DYN);
        attr_set = 1;
    }
    k_cvtsq<<<2049, 256>>>(feat, out);
    k_scan<<<dim3(NTILE, NB), 256, SMEM_DYN>>>();
    k_rcnt<<<64, 256>>>();
    k_assign<<<64, 256>>>();
    k_jump16<<<NTOT / 256, 256>>>(0);
    k_jump16<<<NTOT / 256, 256>>>(1);
    k_jump16<<<NTOT / 256, 256>>>(0);
    k_labfin<<<NTOT / 256, 256>>>();
    k_buildrng<<<1, 1024>>>();
    k_classify<<<32, 128>>>(pts, W1, b1, W2, b2, W3, b3, out);
}